// round 10
// baseline (speedup 1.0000x reference)
#include <cuda_runtime.h>
#include <math.h>

#define B_  64
#define T_  2048
#define IN_ 128
#define H_  256
#define M_  (B_ * T_)

typedef unsigned long long ull;

// ---------------- scratch ----------------
__device__ float g_xp[(size_t)B_ * T_ * H_];    // xp0
__device__ float g_h1[(size_t)B_ * T_ * H_];    // layer-0 hidden states (L2 transport)
__device__ float g_h2last[(size_t)B_ * H_];     // h2[:, T-1, :]
__device__ int   g_f0[64];                      // [g][pair][rank] = steps completed

// ---------------- packed fp32x2 helpers ----------------
__device__ __forceinline__ void fma2(ull &d, ull a, ull b) {
    asm("fma.rn.f32x2 %0, %1, %2, %0;" : "+l"(d) : "l"(a), "l"(b));
}
__device__ __forceinline__ void add2(ull &d, ull a, ull b) {
    asm("add.rn.f32x2 %0, %1, %2;" : "=l"(d) : "l"(a), "l"(b));
}
__device__ __forceinline__ ull splat2(float x) {
    ull r; asm("mov.b64 %0, {%1, %1};" : "=l"(r) : "f"(x)); return r;
}
__device__ __forceinline__ float lo2(ull v) { return __uint_as_float((unsigned)(v & 0xffffffffULL)); }
__device__ __forceinline__ float hi2(ull v) { return __uint_as_float((unsigned)(v >> 32)); }

__device__ __forceinline__ float tanh_fast(float s) {
    s = fminf(fmaxf(s, -15.f), 15.f);
    float e; asm("ex2.approx.f32 %0, %1;" : "=f"(e) : "f"(s * 2.885390082f));
    float r; asm("rcp.approx.f32 %0, %1;" : "=f"(r) : "f"(e + 1.f));
    return fmaf(-2.f, r, 1.f);
}

// ---------------- cluster / mbarrier helpers ----------------
__device__ __forceinline__ unsigned su32(const void* p) {
    return (unsigned)__cvta_generic_to_shared(p);
}
__device__ __forceinline__ unsigned cta_rank() {
    unsigned r; asm("mov.u32 %0, %%cluster_ctarank;" : "=r"(r)); return r;
}
__device__ __forceinline__ unsigned mapa_u32(unsigned addr, unsigned rank) {
    unsigned r; asm("mapa.shared::cluster.u32 %0, %1, %2;" : "=r"(r) : "r"(addr), "r"(rank));
    return r;
}
__device__ __forceinline__ void mbar_init(unsigned addr, unsigned cnt) {
    asm volatile("mbarrier.init.shared.b64 [%0], %1;" :: "r"(addr), "r"(cnt) : "memory");
}
__device__ __forceinline__ void mbar_expect_tx(unsigned addr, unsigned bytes) {
    asm volatile("mbarrier.arrive.expect_tx.shared.b64 _, [%0], %1;" :: "r"(addr), "r"(bytes) : "memory");
}
__device__ __forceinline__ void mbar_arrive_local(unsigned addr) {
    asm volatile("mbarrier.arrive.release.cta.shared.b64 _, [%0];" :: "r"(addr) : "memory");
}
__device__ __forceinline__ void mbar_wait_cluster(unsigned addr, unsigned parity) {
    asm volatile(
        "{\n\t.reg .pred P;\n\t"
        "WL_%=:\n\t"
        "mbarrier.try_wait.parity.acquire.cluster.shared::cta.b64 P, [%0], %1, 0x989680;\n\t"
        "@P bra.uni WD_%=;\n\t"
        "bra.uni WL_%=;\n\t"
        "WD_%=:\n\t}"
        :: "r"(addr), "r"(parity) : "memory");
}
__device__ __forceinline__ void st_async_f32(unsigned raddr, float v, unsigned rmbar) {
    asm volatile(
        "st.async.shared::cluster.mbarrier::complete_tx::bytes.b32 [%0], %1, [%2];"
        :: "r"(raddr), "r"(__float_as_uint(v)), "r"(rmbar) : "memory");
}
__device__ __forceinline__ void cluster_sync_() {
    asm volatile("barrier.cluster.arrive.aligned;" ::: "memory");
    asm volatile("barrier.cluster.wait.aligned;" ::: "memory");
}

// 128-k dot: 32 broadcast LDS.128 + 64 fma2, 4 accumulators
__device__ __forceinline__ float dot128(const float* hb, const ull* wq) {
    ull a0 = 0, a1 = 0, a2 = 0, a3 = 0;
#pragma unroll
    for (int kk = 0; kk < 32; kk += 2) {
        ulonglong2 v0 = *(const ulonglong2*)(hb + kk * 4);
        ulonglong2 v1 = *(const ulonglong2*)(hb + kk * 4 + 4);
        fma2(a0, v0.x, wq[2 * kk]);
        fma2(a1, v0.y, wq[2 * kk + 1]);
        fma2(a2, v1.x, wq[2 * kk + 2]);
        fma2(a3, v1.y, wq[2 * kk + 3]);
    }
    ull s01, s23, s;
    add2(s01, a0, a1); add2(s23, a2, a3); add2(s, s01, s23);
    return lo2(s) + hi2(s);
}

// =====================================================================================
// Phase A: xp0[m][n] = sum_k x[m][k] * W_ih0[n][k] + b_ih0[n] + b_hh0[n]
// =====================================================================================
__global__ __launch_bounds__(256, 2)
void gemm_bias_kernel(const float* __restrict__ A, const float* __restrict__ W,
                      const float* __restrict__ bias0, const float* __restrict__ bias1,
                      float* __restrict__ C, int K)
{
    __shared__ float a_sm[16][132];
    __shared__ float b_sm[16][132];

    const int tid = threadIdx.x;
    const int tx = tid & 15, ty = tid >> 4;
    const int mBase = blockIdx.x * 128;
    const int nBase = blockIdx.y * 128;

    ull acc[8][4];
#pragma unroll
    for (int i = 0; i < 8; i++)
#pragma unroll
        for (int j = 0; j < 4; j++) acc[i][j] = 0ULL;

    for (int kt = 0; kt < K; kt += 16) {
#pragma unroll
        for (int l = 0; l < 2; l++) {
            int idx = l * 256 + tid;
            int row = idx >> 2, kq = idx & 3;
            float4 v = *(const float4*)(A + (size_t)(mBase + row) * K + kt + kq * 4);
            a_sm[kq * 4 + 0][row] = v.x; a_sm[kq * 4 + 1][row] = v.y;
            a_sm[kq * 4 + 2][row] = v.z; a_sm[kq * 4 + 3][row] = v.w;
        }
#pragma unroll
        for (int l = 0; l < 2; l++) {
            int idx = l * 256 + tid;
            int row = idx >> 2, kq = idx & 3;
            float4 v = *(const float4*)(W + (size_t)(nBase + row) * K + kt + kq * 4);
            b_sm[kq * 4 + 0][row] = v.x; b_sm[kq * 4 + 1][row] = v.y;
            b_sm[kq * 4 + 2][row] = v.z; b_sm[kq * 4 + 3][row] = v.w;
        }
        __syncthreads();
#pragma unroll
        for (int kk = 0; kk < 16; kk++) {
            float4 a0 = *(const float4*)&a_sm[kk][ty * 8];
            float4 a1 = *(const float4*)&a_sm[kk][ty * 8 + 4];
            ulonglong2 b0 = *(const ulonglong2*)&b_sm[kk][tx * 8];
            ulonglong2 b1 = *(const ulonglong2*)&b_sm[kk][tx * 8 + 4];
            float av[8] = {a0.x, a0.y, a0.z, a0.w, a1.x, a1.y, a1.z, a1.w};
#pragma unroll
            for (int i = 0; i < 8; i++) {
                ull s = splat2(av[i]);
                fma2(acc[i][0], s, b0.x);
                fma2(acc[i][1], s, b0.y);
                fma2(acc[i][2], s, b1.x);
                fma2(acc[i][3], s, b1.y);
            }
        }
        __syncthreads();
    }

    const int n0 = nBase + tx * 8;
    float bj[8];
#pragma unroll
    for (int j = 0; j < 8; j++) bj[j] = bias0[n0 + j] + bias1[n0 + j];
#pragma unroll
    for (int i = 0; i < 8; i++) {
        int m = mBase + ty * 8 + i;
        float4 o0, o1;
        o0.x = lo2(acc[i][0]) + bj[0]; o0.y = hi2(acc[i][0]) + bj[1];
        o0.z = lo2(acc[i][1]) + bj[2]; o0.w = hi2(acc[i][1]) + bj[3];
        o1.x = lo2(acc[i][2]) + bj[4]; o1.y = hi2(acc[i][2]) + bj[5];
        o1.z = lo2(acc[i][3]) + bj[6]; o1.w = hi2(acc[i][3]) + bj[7];
        *(float4*)(C + (size_t)m * H_ + n0)     = o0;
        *(float4*)(C + (size_t)m * H_ + n0 + 4) = o1;
    }
}

// ---------------- shared layouts for the dual kernel ----------------
struct S0 {                      // layer-0 role (rec3 protocol, 2 rows per pair)
    float h[2][2][264];          // [buf][row][own 0..128 | peer 132..260]
    ull   mbar[2];
};
struct S1 {                      // layer-1 role (partial-sum exchange, 4 rows)
    float h1s[2][4][64];         // staged h1[t] quarter [buf][row][k]
    float h2o[2][4][64];         // own h2 quarter [buf][row][oi]
    float pru[2][64][20];        // partials [buf][oi][row*4+src], 5th float4 = pad
    ull   mbar[2];
};

// =====================================================================================
// Layer-0 role: blocks 64..127. 16 clusters, each = 2 independent 2-CTA pairs.
// Pair (g, p): rows (4g+2p, 4g+2p+1). rec3 lane-pair h-exchange, 2 rows.
// =====================================================================================
__device__ void role0(void* smraw, int g, unsigned rank,
                      const float* __restrict__ xp0, const float* __restrict__ Whh0,
                      float* __restrict__ h1, volatile int* flags)
{
    S0* S = (S0*)smraw;
    const int tid = threadIdx.x;
    const int pairp = (int)rank >> 1, prr = (int)rank & 1;
    const unsigned peer = rank ^ 1u;
    const int row0 = 4 * g + 2 * pairp;
    const int w = tid >> 5, l = tid & 31;
    const int half = l & 1;
    const int o = w * 16 + (l >> 1);
    const int o_glob = prr * 128 + o;
    const int kh = half ? (prr ^ 1) : prr;

    ull wq[64];
    {
        const ulonglong2* src = (const ulonglong2*)(Whh0 + (size_t)o_glob * H_ + kh * 128);
#pragma unroll
        for (int j = 0; j < 32; ++j) { ulonglong2 v = src[j]; wq[2 * j] = v.x; wq[2 * j + 1] = v.y; }
    }

    if (tid == 0) { mbar_init(su32(&S->mbar[0]), 1); mbar_init(su32(&S->mbar[1]), 1); }
    for (int i = tid; i < 2 * 2 * 264; i += 256) ((float*)S->h)[i] = 0.f;
    __syncthreads();
    cluster_sync_();

    const unsigned my_mbar  = su32(&S->mbar[0]);
    const unsigned peer_mbar = mapa_u32(my_mbar, peer);
    const unsigned peer_h    = mapa_u32(su32(&S->h[0][0][0]), peer);

    const size_t xr0 = ((size_t)row0 * T_) * H_ + o_glob;
    const size_t xr1 = ((size_t)(row0 + 1) * T_) * H_ + o_glob;
    float xv0 = 0.f, xv1 = 0.f;
    if (half == 0) { xv0 = __ldg(xp0 + xr0); xv1 = __ldg(xp0 + xr1); }

    const int hoff = half ? 132 : 0;

    for (int t = 0; t < T_; ++t) {
        const int cb = t & 1, nb = cb ^ 1;

        float n0 = 0.f, n1 = 0.f;
        if (half == 0 && t + 1 < T_) {
            n0 = __ldg(xp0 + xr0 + (size_t)(t + 1) * H_);
            n1 = __ldg(xp0 + xr1 + (size_t)(t + 1) * H_);
        }

        if (t > 0)
            mbar_wait_cluster(my_mbar + (unsigned)nb * 8u, (unsigned)((t - 1) >> 1) & 1u);
        if (tid == 0) mbar_expect_tx(my_mbar + (unsigned)cb * 8u, 1024u);

        float p0 = dot128(&S->h[cb][0][hoff], wq);
        float p1 = dot128(&S->h[cb][1][hoff], wq);
        float q0 = __shfl_down_sync(0xffffffffu, p0, 1);
        float q1 = __shfl_down_sync(0xffffffffu, p1, 1);

        if (half == 0) {
            float h0  = tanh_fast(xv0 + p0 + q0);
            float h1v = tanh_fast(xv1 + p1 + q1);
            S->h[nb][0][o] = h0; S->h[nb][1][o] = h1v;
            st_async_f32(peer_h + (unsigned)((nb * 2 + 0) * 264 + 132 + o) * 4u,
                         h0, peer_mbar + (unsigned)cb * 8u);
            st_async_f32(peer_h + (unsigned)((nb * 2 + 1) * 264 + 132 + o) * 4u,
                         h1v, peer_mbar + (unsigned)cb * 8u);
            h1[xr0 + (size_t)t * H_] = h0;
            h1[xr1 + (size_t)t * H_] = h1v;
        }

        if ((t & 3) == 3) {
            __threadfence();
            __syncthreads();
            if (tid == 0) flags[g * 4 + pairp * 2 + prr] = t + 1;
        } else {
            __syncthreads();
        }
        xv0 = n0; xv1 = n1;
    }
    mbar_wait_cluster(my_mbar + (unsigned)((T_ - 1) & 1) * 8u,
                      (unsigned)((T_ - 1) >> 1) & 1u);
    cluster_sync_();
}

// =====================================================================================
// Layer-1 role: blocks 0..63. 16 clusters x 4 CTAs, 4 rows per cluster.
// Rank r owns k-quarter Kr=[64r,64r+64) and outputs [64r,64r+64).
// p[o,row] = Wih1[o,Kr] @ h1[row][t] + Whh1[o,Kr] @ h2own[row][t-1].
// Remote partials via 4x st.async.b32 (tx mbar), self via STS + local arrive.
// Arrive count 65 = 64 self threads + 1 expect_tx armer. h1 streamed from global
// behind layer-0 flags with 1-step prefetch.
// =====================================================================================
__device__ void role1(void* smraw, int cc, unsigned rank,
                      const float* __restrict__ Wih1, const float* __restrict__ Whh1,
                      const float* __restrict__ bih1, const float* __restrict__ bhh1,
                      const float* __restrict__ h1, volatile int* flags,
                      float* __restrict__ h2last)
{
    S1* S = (S1*)smraw;
    const int tid = threadIdx.x;
    const int d = tid >> 6, oi = tid & 63;
    const int O = 64 * d + oi;
    const bool self = (d == (int)rank);
    const int erow = d, eoi = oi;                   // epilogue aliases
    const int lrow = d, lk = oi;                    // h1-load aliases
    const int Eo = 64 * (int)rank + eoi;

    ull wI[32], wH[32];
#pragma unroll
    for (int j = 0; j < 16; ++j) {
        ulonglong2 a = *(const ulonglong2*)(Wih1 + (size_t)O * H_ + (int)rank * 64 + j * 4);
        wI[2 * j] = a.x; wI[2 * j + 1] = a.y;
        ulonglong2 b = *(const ulonglong2*)(Whh1 + (size_t)O * H_ + (int)rank * 64 + j * 4);
        wH[2 * j] = b.x; wH[2 * j + 1] = b.y;
    }
    const float ebias = bih1[Eo] + bhh1[Eo];

    if (tid == 0) { mbar_init(su32(&S->mbar[0]), 65); mbar_init(su32(&S->mbar[1]), 65); }
    for (int i = tid; i < 2 * 4 * 64; i += 256) {
        ((float*)S->h1s)[i] = 0.f; ((float*)S->h2o)[i] = 0.f;
    }
    __syncthreads();
    cluster_sync_();

    const unsigned my_mbar = su32(&S->mbar[0]);
    const unsigned dmb  = mapa_u32(my_mbar, (unsigned)d);
    const unsigned dpru = mapa_u32(su32(&S->pru[0][0][0]), (unsigned)d)
                        + (unsigned)(oi * 20 + (int)rank) * 4u;   // + row*16B

    volatile const int* fA = flags + cc * 4 + 0 * 2 + ((int)rank >> 1);
    volatile const int* fB = flags + cc * 4 + 1 * 2 + ((int)rank >> 1);
    int seen = 0;

    // preload h1[0]
    while (seen < 1) { int a = *fA, b = *fB; seen = a < b ? a : b; }
    {
        float v = __ldg(h1 + ((size_t)(4 * cc + lrow) * T_) * H_ + (size_t)((int)rank * 64 + lk));
        S->h1s[0][lrow][lk] = v;
    }
    __syncthreads();

    for (int t = 0; t < T_; ++t) {
        const int cb = t & 1, nb = cb ^ 1;

        if (tid == 0) mbar_expect_tx(my_mbar + (unsigned)cb * 8u, 3072u);

        // prefetch h1[t+1]
        float h1n = 0.f;
        if (t + 1 < T_) {
            if (seen < t + 2) {
                do { int a = *fA, b = *fB; seen = a < b ? a : b; } while (seen < t + 2);
            }
            h1n = __ldg(h1 + ((size_t)(4 * cc + lrow) * T_ + (t + 1)) * H_
                           + (size_t)((int)rank * 64 + lk));
        }

        // matvec: 4 rows, both matrices over own k-quarter
        float p[4];
#pragma unroll
        for (int r4 = 0; r4 < 4; ++r4) {
            const float* ha = &S->h1s[cb][r4][0];
            const float* hb = &S->h2o[cb][r4][0];
            ull a0 = 0, a1 = 0, a2 = 0, a3 = 0;
#pragma unroll
            for (int j = 0; j < 16; ++j) {
                ulonglong2 u  = *(const ulonglong2*)(ha + j * 4);
                ulonglong2 g2 = *(const ulonglong2*)(hb + j * 4);
                fma2(a0, u.x,  wI[2 * j]); fma2(a1, u.y,  wI[2 * j + 1]);
                fma2(a2, g2.x, wH[2 * j]); fma2(a3, g2.y, wH[2 * j + 1]);
            }
            ull s01, s23, s;
            add2(s01, a0, a1); add2(s23, a2, a3); add2(s, s01, s23);
            p[r4] = lo2(s) + hi2(s);
        }

        // ship partials (phase t)
        if (self) {
            float* pb = &S->pru[cb][oi][0];
            pb[0 * 4 + (int)rank] = p[0];
            pb[1 * 4 + (int)rank] = p[1];
            pb[2 * 4 + (int)rank] = p[2];
            pb[3 * 4 + (int)rank] = p[3];
            mbar_arrive_local(my_mbar + (unsigned)cb * 8u);
        } else {
            unsigned base = dpru + (unsigned)cb * 5120u;
            unsigned mb   = dmb + (unsigned)cb * 8u;
            st_async_f32(base +  0u, p[0], mb);
            st_async_f32(base + 16u, p[1], mb);
            st_async_f32(base + 32u, p[2], mb);
            st_async_f32(base + 48u, p[3], mb);
        }

        // epilogue
        mbar_wait_cluster(my_mbar + (unsigned)cb * 8u, (unsigned)(t >> 1) & 1u);
        float4 pv = *(const float4*)&S->pru[cb][eoi][erow * 4];
        float h = tanh_fast(ebias + pv.x + pv.y + pv.z + pv.w);
        S->h2o[nb][erow][eoi] = h;
        if (t == T_ - 1) h2last[(size_t)(4 * cc + erow) * H_ + Eo] = h;
        if (t + 1 < T_) S->h1s[nb][lrow][lk] = h1n;
        __syncthreads();
    }
    cluster_sync_();
}

// =====================================================================================
// Dual kernel: 128 CTAs, cluster 4. Blocks 0..63 = layer-1; 64..127 = layer-0.
// =====================================================================================
__global__ void __cluster_dims__(4, 1, 1) __launch_bounds__(256, 1)
rnn_dual(const float* __restrict__ xp0, const float* __restrict__ Whh0,
         const float* __restrict__ Wih1, const float* __restrict__ Whh1,
         const float* __restrict__ bih1, const float* __restrict__ bhh1,
         float* __restrict__ h1, float* __restrict__ h2last, int* flags)
{
    __shared__ __align__(16) unsigned char smraw[sizeof(S1) > sizeof(S0) ? sizeof(S1) : sizeof(S0)];
    const int cid = blockIdx.x >> 2;
    const unsigned rank = cta_rank();
    if (cid < 16)
        role1(smraw, cid, rank, Wih1, Whh1, bih1, bhh1, h1, (volatile int*)flags, h2last);
    else
        role0(smraw, cid - 16, rank, xp0, Whh0, h1, (volatile int*)flags);
}

// =====================================================================================
// Final FC: out[b] = dot(h2last[b, :], W_fc[0,:]) + b_fc[0]
// =====================================================================================
__global__ void fc_kernel(const float* __restrict__ h2l, const float* __restrict__ Wfc,
                          const float* __restrict__ bfc, float* __restrict__ out)
{
    __shared__ float red[8];
    int b = blockIdx.x, tid = threadIdx.x;
    float v = h2l[(size_t)b * H_ + tid] * Wfc[tid];
#pragma unroll
    for (int o = 16; o > 0; o >>= 1) v += __shfl_down_sync(0xffffffffu, v, o);
    if ((tid & 31) == 0) red[tid >> 5] = v;
    __syncthreads();
    if (tid < 8) {
        float s = red[tid];
#pragma unroll
        for (int o = 4; o > 0; o >>= 1) s += __shfl_down_sync(0xffu, s, o);
        if (tid == 0) out[b] = s + bfc[0];
    }
}

// =====================================================================================
extern "C" void kernel_launch(void* const* d_in, const int* in_sizes, int n_in,
                              void* d_out, int out_size)
{
    const float* x     = (const float*)d_in[0];
    const float* W_ih0 = (const float*)d_in[1];
    const float* W_hh0 = (const float*)d_in[2];
    const float* b_ih0 = (const float*)d_in[3];
    const float* b_hh0 = (const float*)d_in[4];
    const float* W_ih1 = (const float*)d_in[5];
    const float* W_hh1 = (const float*)d_in[6];
    const float* b_ih1 = (const float*)d_in[7];
    const float* b_hh1 = (const float*)d_in[8];
    const float* W_fc  = (const float*)d_in[9];
    const float* b_fc  = (const float*)d_in[10];
    float* out = (float*)d_out;

    float *xp, *h1, *h2l; int* flags;
    cudaGetSymbolAddress((void**)&xp, g_xp);
    cudaGetSymbolAddress((void**)&h1, g_h1);
    cudaGetSymbolAddress((void**)&h2l, g_h2last);
    cudaGetSymbolAddress((void**)&flags, g_f0);

    // reset layer-0 completion flags (captured memset node; re-runs each replay)
    cudaMemsetAsync(flags, 0, 64 * sizeof(int), 0);

    dim3 ggemm(M_ / 128, H_ / 128);

    // Phase A: xp0 = x @ W_ih0^T + b_ih0 + b_hh0
    gemm_bias_kernel<<<ggemm, 256>>>(x, W_ih0, b_ih0, b_hh0, xp, IN_);
    // Phase B: both recurrences overlapped in one kernel (layer-1 folds in xp1 GEMM)
    rnn_dual<<<128, 256>>>(xp, W_hh0, W_ih1, W_hh1, b_ih1, b_hh1, h1, h2l, flags);
    // Phase C: final projection
    fc_kernel<<<B_, H_>>>(h2l, W_fc, b_fc, out);
}

// round 11
// speedup vs baseline: 1.2679x; 1.2679x over previous
#include <cuda_runtime.h>
#include <math.h>

#define B_  64
#define T_  2048
#define IN_ 128
#define H_  256
#define M_  (B_ * T_)

typedef unsigned long long ull;

// ---------------- scratch ----------------
__device__ float g_xp [(size_t)B_ * T_ * H_];   // xp0
__device__ float g_xp1[(size_t)B_ * T_ * H_];   // xp1 (GEMM role -> L1)
__device__ float g_h1 [(size_t)B_ * T_ * H_];   // h1 (L0 -> GEMM role)
__device__ float g_h2last[(size_t)B_ * H_];
__device__ int   g_f0[32];                      // [pair*2+rank] h1 steps done
__device__ int   g_fx[64];                      // [row] xp1 steps done

// ---------------- packed fp32x2 helpers ----------------
__device__ __forceinline__ void fma2(ull &d, ull a, ull b) {
    asm("fma.rn.f32x2 %0, %1, %2, %0;" : "+l"(d) : "l"(a), "l"(b));
}
__device__ __forceinline__ void add2(ull &d, ull a, ull b) {
    asm("add.rn.f32x2 %0, %1, %2;" : "=l"(d) : "l"(a), "l"(b));
}
__device__ __forceinline__ ull splat2(float x) {
    ull r; asm("mov.b64 %0, {%1, %1};" : "=l"(r) : "f"(x)); return r;
}
__device__ __forceinline__ float lo2(ull v) { return __uint_as_float((unsigned)(v & 0xffffffffULL)); }
__device__ __forceinline__ float hi2(ull v) { return __uint_as_float((unsigned)(v >> 32)); }

__device__ __forceinline__ float tanh_fast(float s) {
    s = fminf(fmaxf(s, -15.f), 15.f);
    float e; asm("ex2.approx.f32 %0, %1;" : "=f"(e) : "f"(s * 2.885390082f));
    float r; asm("rcp.approx.f32 %0, %1;" : "=f"(r) : "f"(e + 1.f));
    return fmaf(-2.f, r, 1.f);
}

// ---------------- cluster / mbarrier helpers (rec3-proven) ----------------
__device__ __forceinline__ unsigned su32(const void* p) {
    return (unsigned)__cvta_generic_to_shared(p);
}
__device__ __forceinline__ unsigned mapa_u32(unsigned addr, unsigned rank) {
    unsigned r; asm("mapa.shared::cluster.u32 %0, %1, %2;" : "=r"(r) : "r"(addr), "r"(rank));
    return r;
}
__device__ __forceinline__ void mbar_init(unsigned addr, unsigned cnt) {
    asm volatile("mbarrier.init.shared.b64 [%0], %1;" :: "r"(addr), "r"(cnt) : "memory");
}
__device__ __forceinline__ void mbar_expect_tx(unsigned addr, unsigned bytes) {
    asm volatile("mbarrier.arrive.expect_tx.shared.b64 _, [%0], %1;" :: "r"(addr), "r"(bytes) : "memory");
}
__device__ __forceinline__ void mbar_wait_cluster(unsigned addr, unsigned parity) {
    asm volatile(
        "{\n\t.reg .pred P;\n\t"
        "WL_%=:\n\t"
        "mbarrier.try_wait.parity.acquire.cluster.shared::cta.b64 P, [%0], %1, 0x989680;\n\t"
        "@P bra.uni WD_%=;\n\t"
        "bra.uni WL_%=;\n\t"
        "WD_%=:\n\t}"
        :: "r"(addr), "r"(parity) : "memory");
}
__device__ __forceinline__ void st_async_f32(unsigned raddr, float v, unsigned rmbar) {
    asm volatile(
        "st.async.shared::cluster.mbarrier::complete_tx::bytes.b32 [%0], %1, [%2];"
        :: "r"(raddr), "r"(__float_as_uint(v)), "r"(rmbar) : "memory");
}
__device__ __forceinline__ void cluster_sync_() {
    asm volatile("barrier.cluster.arrive.aligned;" ::: "memory");
    asm volatile("barrier.cluster.wait.aligned;" ::: "memory");
}

// 128-k dot: 32 broadcast LDS.128 + 64 fma2
__device__ __forceinline__ float dot128(const float* hb, const ull* wq) {
    ull a0 = 0, a1 = 0, a2 = 0, a3 = 0;
#pragma unroll
    for (int kk = 0; kk < 32; kk += 2) {
        ulonglong2 v0 = *(const ulonglong2*)(hb + kk * 4);
        ulonglong2 v1 = *(const ulonglong2*)(hb + kk * 4 + 4);
        fma2(a0, v0.x, wq[2 * kk]);
        fma2(a1, v0.y, wq[2 * kk + 1]);
        fma2(a2, v1.x, wq[2 * kk + 2]);
        fma2(a3, v1.y, wq[2 * kk + 3]);
    }
    ull s01, s23, s;
    add2(s01, a0, a1); add2(s23, a2, a3); add2(s, s01, s23);
    return lo2(s) + hi2(s);
}

// =====================================================================================
// Phase A GEMM (proven): xp0 = x @ W_ih0^T + b_ih0 + b_hh0
// =====================================================================================
__global__ __launch_bounds__(256, 2)
void gemm_bias_kernel(const float* __restrict__ A, const float* __restrict__ W,
                      const float* __restrict__ bias0, const float* __restrict__ bias1,
                      float* __restrict__ C, int K)
{
    __shared__ float a_sm[16][132];
    __shared__ float b_sm[16][132];
    const int tid = threadIdx.x;
    const int tx = tid & 15, ty = tid >> 4;
    const int mBase = blockIdx.x * 128, nBase = blockIdx.y * 128;

    ull acc[8][4];
#pragma unroll
    for (int i = 0; i < 8; i++)
#pragma unroll
        for (int j = 0; j < 4; j++) acc[i][j] = 0ULL;

    for (int kt = 0; kt < K; kt += 16) {
#pragma unroll
        for (int l = 0; l < 2; l++) {
            int idx = l * 256 + tid, row = idx >> 2, kq = idx & 3;
            float4 v = *(const float4*)(A + (size_t)(mBase + row) * K + kt + kq * 4);
            a_sm[kq * 4 + 0][row] = v.x; a_sm[kq * 4 + 1][row] = v.y;
            a_sm[kq * 4 + 2][row] = v.z; a_sm[kq * 4 + 3][row] = v.w;
        }
#pragma unroll
        for (int l = 0; l < 2; l++) {
            int idx = l * 256 + tid, row = idx >> 2, kq = idx & 3;
            float4 v = *(const float4*)(W + (size_t)(nBase + row) * K + kt + kq * 4);
            b_sm[kq * 4 + 0][row] = v.x; b_sm[kq * 4 + 1][row] = v.y;
            b_sm[kq * 4 + 2][row] = v.z; b_sm[kq * 4 + 3][row] = v.w;
        }
        __syncthreads();
#pragma unroll
        for (int kk = 0; kk < 16; kk++) {
            float4 a0 = *(const float4*)&a_sm[kk][ty * 8];
            float4 a1 = *(const float4*)&a_sm[kk][ty * 8 + 4];
            ulonglong2 b0 = *(const ulonglong2*)&b_sm[kk][tx * 8];
            ulonglong2 b1 = *(const ulonglong2*)&b_sm[kk][tx * 8 + 4];
            float av[8] = {a0.x, a0.y, a0.z, a0.w, a1.x, a1.y, a1.z, a1.w};
#pragma unroll
            for (int i = 0; i < 8; i++) {
                ull s = splat2(av[i]);
                fma2(acc[i][0], s, b0.x); fma2(acc[i][1], s, b0.y);
                fma2(acc[i][2], s, b1.x); fma2(acc[i][3], s, b1.y);
            }
        }
        __syncthreads();
    }
    const int n0 = nBase + tx * 8;
    float bj[8];
#pragma unroll
    for (int j = 0; j < 8; j++) bj[j] = bias0[n0 + j] + bias1[n0 + j];
#pragma unroll
    for (int i = 0; i < 8; i++) {
        int m = mBase + ty * 8 + i;
        float4 o0, o1;
        o0.x = lo2(acc[i][0]) + bj[0]; o0.y = hi2(acc[i][0]) + bj[1];
        o0.z = lo2(acc[i][1]) + bj[2]; o0.w = hi2(acc[i][1]) + bj[3];
        o1.x = lo2(acc[i][2]) + bj[4]; o1.y = hi2(acc[i][2]) + bj[5];
        o1.z = lo2(acc[i][3]) + bj[6]; o1.w = hi2(acc[i][3]) + bj[7];
        *(float4*)(C + (size_t)m * H_ + n0)     = o0;
        *(float4*)(C + (size_t)m * H_ + n0 + 4) = o1;
    }
}

// =====================================================================================
// Rec role (shared by L0 / L1): rec3 lane-pair protocol, 4 rows per 2-CTA pair.
// GATED: L1 reads xpin behind fx flags (poll amortized, in prefetch shadow).
// =====================================================================================
template<bool GATED>
__device__ void role_rec(float* smf, int p, int rank,
                         const float* __restrict__ xpin, const float* __restrict__ Whh,
                         float* __restrict__ hout,        // L0: h1 stream; L1: h2last
                         volatile int* myflags,           // L0: f0 (set); L1: fx (read)
                         const float* dummy)
{
    float (*h_sm)[4][264] = (float(*)[4][264])smf;          // [buf][row][own|peer@132]
    ull* mbar = (ull*)(smf + 2 * 4 * 264);

    const int tid = threadIdx.x;
    const int w = tid >> 5, l = tid & 31;
    const int half = l & 1;
    const int o = w * 16 + (l >> 1);
    const int o_glob = rank * 128 + o;
    const int kh = half ? (rank ^ 1) : rank;
    const int row0 = 4 * p;

    ull wq[64];
    {
        const ulonglong2* src = (const ulonglong2*)(Whh + (size_t)o_glob * H_ + kh * 128);
#pragma unroll
        for (int j = 0; j < 32; ++j) { ulonglong2 v = src[j]; wq[2 * j] = v.x; wq[2 * j + 1] = v.y; }
    }

    if (tid == 0) { mbar_init(su32(&mbar[0]), 1); mbar_init(su32(&mbar[1]), 1); }
    for (int i = tid; i < 2 * 4 * 264; i += 256) smf[i] = 0.f;
    __syncthreads();
    cluster_sync_();

    const unsigned my_mbar   = su32(&mbar[0]);
    const unsigned peer_mbar = mapa_u32(my_mbar, (unsigned)(rank ^ 1));
    const unsigned peer_h    = mapa_u32(su32(&h_sm[0][0][0]), (unsigned)(rank ^ 1));
    const int hoff = half ? 132 : 0;

    size_t xr[4];
#pragma unroll
    for (int r = 0; r < 4; ++r) xr[r] = ((size_t)(row0 + r) * T_) * H_ + o_glob;

    int seen = 0;
    float xv[4] = {0.f, 0.f, 0.f, 0.f};
    if (half == 0) {
        if (GATED) {
            while (seen < 1) {
                int m0 = myflags[row0], m1 = myflags[row0 + 1];
                int m2 = myflags[row0 + 2], m3 = myflags[row0 + 3];
                seen = min(min(m0, m1), min(m2, m3));
            }
#pragma unroll
            for (int r = 0; r < 4; ++r) xv[r] = __ldcg(xpin + xr[r]);
        } else {
#pragma unroll
            for (int r = 0; r < 4; ++r) xv[r] = __ldg(xpin + xr[r]);
        }
    }

    for (int t = 0; t < T_; ++t) {
        const int cb = t & 1, nb = cb ^ 1;

        // prefetch xp for t+1 (flag poll amortized: fx jumps by 32)
        float xvn[4] = {0.f, 0.f, 0.f, 0.f};
        if (half == 0 && t + 1 < T_) {
            if (GATED && seen < t + 2) {
                do {
                    int m0 = myflags[row0], m1 = myflags[row0 + 1];
                    int m2 = myflags[row0 + 2], m3 = myflags[row0 + 3];
                    seen = min(min(m0, m1), min(m2, m3));
                } while (seen < t + 2);
            }
            if (GATED) {
#pragma unroll
                for (int r = 0; r < 4; ++r) xvn[r] = __ldcg(xpin + xr[r] + (size_t)(t + 1) * H_);
            } else {
#pragma unroll
                for (int r = 0; r < 4; ++r) xvn[r] = __ldg(xpin + xr[r] + (size_t)(t + 1) * H_);
            }
        }

        if (t > 0)
            mbar_wait_cluster(my_mbar + (unsigned)nb * 8u, (unsigned)((t - 1) >> 1) & 1u);
        if (tid == 0) mbar_expect_tx(my_mbar + (unsigned)cb * 8u, 2048u);

        float pr[4], qr[4];
#pragma unroll
        for (int r = 0; r < 4; ++r) pr[r] = dot128(&h_sm[cb][r][hoff], wq);
#pragma unroll
        for (int r = 0; r < 4; ++r) qr[r] = __shfl_down_sync(0xffffffffu, pr[r], 1);

        if (half == 0) {
#pragma unroll
            for (int r = 0; r < 4; ++r) {
                float h = tanh_fast(xv[r] + pr[r] + qr[r]);
                h_sm[nb][r][o] = h;
                st_async_f32(peer_h + (unsigned)((nb * 4 + r) * 264 + 132 + o) * 4u,
                             h, peer_mbar + (unsigned)cb * 8u);
                if (!GATED)
                    hout[xr[r] + (size_t)t * H_] = h;                 // stream h1
                else if (t == T_ - 1)
                    hout[(size_t)(row0 + r) * H_ + o_glob] = h;       // h2last
            }
        }

        if (!GATED && (t & 7) == 7) {
            __threadfence();
            __syncthreads();
            if (tid == 0) myflags[p * 2 + rank] = t + 1;
        } else {
            __syncthreads();
        }
#pragma unroll
        for (int r = 0; r < 4; ++r) xv[r] = xvn[r];
    }
    mbar_wait_cluster(my_mbar + (unsigned)((T_ - 1) & 1) * 8u,
                      (unsigned)((T_ - 1) >> 1) & 1u);
    cluster_sync_();
}

// =====================================================================================
// GEMM role: CTA per batch row; stream xp1[b, t0:t0+32, :] = h1 @ Wih1^T + biases.
// =====================================================================================
__device__ void role_gemm(float* smf, int b,
                          const float* __restrict__ h1, const float* __restrict__ Wih1,
                          const float* __restrict__ bih1, const float* __restrict__ bhh1,
                          float* __restrict__ xp1, volatile int* f0, volatile int* fx)
{
    float (*Asm)[36]  = (float(*)[36])smf;                    // [16][36]
    float (*Wsm)[260] = (float(*)[260])(smf + 16 * 36);       // [16][260]

    const int tid = threadIdx.x;
    const int tx = tid & 31, ty = tid >> 5;
    const int n0 = tx * 8;
    const int pair = b >> 2;

    float bj[8];
#pragma unroll
    for (int j = 0; j < 8; ++j) bj[j] = bih1[n0 + j] + bhh1[n0 + j];

    for (int t0 = 0; t0 < T_; t0 += 32) {
        // wait for h1[b, t0 .. t0+31] (both ranks of the producing pair)
        for (;;) {
            int a = f0[pair * 2], c = f0[pair * 2 + 1];
            if (min(a, c) >= t0 + 32) break;
        }

        ull acc[4][4];
#pragma unroll
        for (int i = 0; i < 4; ++i)
#pragma unroll
            for (int j = 0; j < 4; ++j) acc[i][j] = 0ULL;

        for (int kt = 0; kt < 256; kt += 16) {
            if (tid < 128) {
                int m = tid >> 2, kq = tid & 3;
                float4 v = __ldcg((const float4*)(h1 + ((size_t)b * T_ + t0 + m) * H_ + kt + kq * 4));
                Asm[kq * 4 + 0][m] = v.x; Asm[kq * 4 + 1][m] = v.y;
                Asm[kq * 4 + 2][m] = v.z; Asm[kq * 4 + 3][m] = v.w;
            }
#pragma unroll
            for (int j = 0; j < 4; ++j) {
                float4 v = __ldg((const float4*)(Wih1 + (size_t)tid * H_ + kt + j * 4));
                Wsm[j * 4 + 0][tid] = v.x; Wsm[j * 4 + 1][tid] = v.y;
                Wsm[j * 4 + 2][tid] = v.z; Wsm[j * 4 + 3][tid] = v.w;
            }
            __syncthreads();
#pragma unroll
            for (int kk = 0; kk < 16; ++kk) {
                float4 a = *(const float4*)&Asm[kk][ty * 4];
                ulonglong2 w0 = *(const ulonglong2*)&Wsm[kk][tx * 8];
                ulonglong2 w1 = *(const ulonglong2*)&Wsm[kk][tx * 8 + 4];
                float av[4] = {a.x, a.y, a.z, a.w};
#pragma unroll
                for (int i = 0; i < 4; ++i) {
                    ull s = splat2(av[i]);
                    fma2(acc[i][0], s, w0.x); fma2(acc[i][1], s, w0.y);
                    fma2(acc[i][2], s, w1.x); fma2(acc[i][3], s, w1.y);
                }
            }
            __syncthreads();
        }

#pragma unroll
        for (int i = 0; i < 4; ++i) {
            int m = ty * 4 + i;
            float4 o0, o1;
            o0.x = lo2(acc[i][0]) + bj[0]; o0.y = hi2(acc[i][0]) + bj[1];
            o0.z = lo2(acc[i][1]) + bj[2]; o0.w = hi2(acc[i][1]) + bj[3];
            o1.x = lo2(acc[i][2]) + bj[4]; o1.y = hi2(acc[i][2]) + bj[5];
            o1.z = lo2(acc[i][3]) + bj[6]; o1.w = hi2(acc[i][3]) + bj[7];
            *(float4*)(xp1 + ((size_t)b * T_ + t0 + m) * H_ + n0)     = o0;
            *(float4*)(xp1 + ((size_t)b * T_ + t0 + m) * H_ + n0 + 4) = o1;
        }
        __threadfence();
        __syncthreads();
        if (tid == 0) fx[b] = t0 + 32;
    }
}

// =====================================================================================
// Pipeline kernel: blocks [0,32)=L0 rec, [32,96)=GEMM role, [96,128)=L1 rec.
// =====================================================================================
__global__ void __cluster_dims__(2, 1, 1) __launch_bounds__(256, 1)
rnn_pipe(const float* __restrict__ xp0, const float* __restrict__ Whh0,
         const float* __restrict__ Wih1, const float* __restrict__ Whh1,
         const float* __restrict__ bih1, const float* __restrict__ bhh1,
         float* __restrict__ h1, float* __restrict__ xp1,
         float* __restrict__ h2last, int* f0, int* fx)
{
    __shared__ __align__(16) float smf[16 * 36 + 16 * 260 + 16];   // max(rec 2120, gemm 4736)
    const int blk = blockIdx.x;
    if (blk < 32) {
        role_rec<false>(smf, blk >> 1, blk & 1, xp0, Whh0, h1, (volatile int*)f0, 0);
    } else if (blk < 96) {
        role_gemm(smf, blk - 32, h1, Wih1, bih1, bhh1, xp1, (volatile int*)f0, (volatile int*)fx);
    } else {
        const int q = blk - 96;
        role_rec<true>(smf, q >> 1, q & 1, xp1, Whh1, h2last, (volatile int*)fx, 0);
    }
}

// =====================================================================================
// Final FC
// =====================================================================================
__global__ void fc_kernel(const float* __restrict__ h2l, const float* __restrict__ Wfc,
                          const float* __restrict__ bfc, float* __restrict__ out)
{
    __shared__ float red[8];
    int b = blockIdx.x, tid = threadIdx.x;
    float v = h2l[(size_t)b * H_ + tid] * Wfc[tid];
#pragma unroll
    for (int o = 16; o > 0; o >>= 1) v += __shfl_down_sync(0xffffffffu, v, o);
    if ((tid & 31) == 0) red[tid >> 5] = v;
    __syncthreads();
    if (tid < 8) {
        float s = red[tid];
#pragma unroll
        for (int o = 4; o > 0; o >>= 1) s += __shfl_down_sync(0xffu, s, o);
        if (tid == 0) out[b] = s + bfc[0];
    }
}

// =====================================================================================
extern "C" void kernel_launch(void* const* d_in, const int* in_sizes, int n_in,
                              void* d_out, int out_size)
{
    const float* x     = (const float*)d_in[0];
    const float* W_ih0 = (const float*)d_in[1];
    const float* W_hh0 = (const float*)d_in[2];
    const float* b_ih0 = (const float*)d_in[3];
    const float* b_hh0 = (const float*)d_in[4];
    const float* W_ih1 = (const float*)d_in[5];
    const float* W_hh1 = (const float*)d_in[6];
    const float* b_ih1 = (const float*)d_in[7];
    const float* b_hh1 = (const float*)d_in[8];
    const float* W_fc  = (const float*)d_in[9];
    const float* b_fc  = (const float*)d_in[10];
    float* out = (float*)d_out;

    float *xp, *xp1, *h1, *h2l; int *f0, *fx;
    cudaGetSymbolAddress((void**)&xp,  g_xp);
    cudaGetSymbolAddress((void**)&xp1, g_xp1);
    cudaGetSymbolAddress((void**)&h1,  g_h1);
    cudaGetSymbolAddress((void**)&h2l, g_h2last);
    cudaGetSymbolAddress((void**)&f0,  g_f0);
    cudaGetSymbolAddress((void**)&fx,  g_fx);

    cudaMemsetAsync(f0, 0, 32 * sizeof(int), 0);
    cudaMemsetAsync(fx, 0, 64 * sizeof(int), 0);

    dim3 ggemm(M_ / 128, H_ / 128);
    // Phase A: xp0 = x @ W_ih0^T + b_ih0 + b_hh0
    gemm_bias_kernel<<<ggemm, 256>>>(x, W_ih0, b_ih0, b_hh0, xp, IN_);
    // Phase B: overlapped L0-rec | xp1-GEMM | L1-rec pipeline
    rnn_pipe<<<128, 256>>>(xp, W_hh0, W_ih1, W_hh1, b_ih1, b_hh1, h1, xp1, h2l, f0, fx);
    // Phase C: final projection
    fc_kernel<<<B_, H_>>>(h2l, W_fc, b_fc, out);
}